// round 2
// baseline (speedup 1.0000x reference)
#include <cuda_runtime.h>
#include <cstdint>

// Problem constants (fixed by the dataset's setup_inputs)
#define NN   40000
#define EE   400000
#define EP   (EE + NN)     // edges + self loops
#define HH   8
#define CC   64
#define HC   512           // H*C
#define FF   16
#define RR   40            // n_routes1 == n_routes2 == 40
#define KOUT 39            // max_to_swap - 1
#define WCOL 61            // MAXR + 1 columns of W_head
#define NLOG (RR * RR * KOUT)

// ---------------- scratch (reused across the two graphs, stream-ordered) ---
__device__ float g_h[(size_t)NN * HC];        // 82 MB — L2 resident
__device__ float g_as[NN * HH];
__device__ float g_ad[NN * HH];
__device__ float g_exs[(size_t)EP * HH];      // dst-sorted exp values, 14 MB
__device__ int   g_deg[NN];
__device__ int   g_rowptr[NN + 1];
__device__ int   g_cursor[NN];
__device__ int   g_srcs[EP];                  // dst-sorted src ids
__device__ float g_agg[2][RR * HC];
__device__ int   g_cnt[2][RR];
__device__ float g_U[2][RR * 64];
__device__ float g_logits[NLOG];

__device__ __forceinline__ void red4(float* p, float4 v) {
    asm volatile("red.global.add.v4.f32 [%0], {%1, %2, %3, %4};"
                 :: "l"(p), "f"(v.x), "f"(v.y), "f"(v.z), "f"(v.w) : "memory");
}

// ---------------- per-graph init (+ route node counts) ---------------------
__global__ void k_init(int g, const int* __restrict__ route_vec) {
    int i = blockIdx.x * blockDim.x + threadIdx.x;
    if (i < NN) {
        g_deg[i] = 1;  // self loop
        atomicAdd(&g_cnt[g][route_vec[i]], 1);
    }
    if (i < RR * HC) g_agg[g][i] = 0.f;
}

__global__ void k_zero(int g) {
    int i = threadIdx.x;
    if (i < RR) g_cnt[g][i] = 0;
}

// ---------------- fused GEMM h = x@W + attention dots ----------------------
__global__ __launch_bounds__(256) void k_gemm(
    const float* __restrict__ x, const float* __restrict__ W,
    const float* __restrict__ attS, const float* __restrict__ attD)
{
    __shared__ float Wsh[FF * HC];  // 32 KB
    int t = threadIdx.x;
    for (int i = t; i < FF * HC; i += blockDim.x) Wsh[i] = W[i];
    __syncthreads();

    int l    = t & 31;
    int wid  = blockIdx.x * (blockDim.x >> 5) + (t >> 5);
    int nwrp = gridDim.x * (blockDim.x >> 5);

    for (int n = wid; n < NN; n += nwrp) {
        float v = (l < FF) ? x[n * FF + l] : 0.f;
        float xr[FF];
        #pragma unroll
        for (int f = 0; f < FF; f++) xr[f] = __shfl_sync(0xffffffffu, v, f);

        float hacc[16];
        #pragma unroll
        for (int k = 0; k < 16; k++) {
            float a = 0.f;
            #pragma unroll
            for (int f = 0; f < FF; f++)
                a = fmaf(xr[f], Wsh[f * HC + 32 * k + l], a);
            hacc[k] = a;
            g_h[(size_t)n * HC + 32 * k + l] = a;   // coalesced 128B per k
        }
        #pragma unroll
        for (int h = 0; h < HH; h++) {
            float ps = fmaf(hacc[2*h],   attS[h*64 + l],
                      hacc[2*h+1] * attS[h*64 + 32 + l]);
            float pd = fmaf(hacc[2*h],   attD[h*64 + l],
                      hacc[2*h+1] * attD[h*64 + 32 + l]);
            #pragma unroll
            for (int o = 16; o > 0; o >>= 1) {
                ps += __shfl_xor_sync(0xffffffffu, ps, o);
                pd += __shfl_xor_sync(0xffffffffu, pd, o);
            }
            if (l == 0) { g_as[n*HH + h] = ps; g_ad[n*HH + h] = pd; }
        }
    }
}

// ---------------- degree histogram -----------------------------------------
__global__ void k_deg(const int* __restrict__ ei) {
    int i = blockIdx.x * blockDim.x + threadIdx.x;
    if (i < EE) atomicAdd(&g_deg[ei[EE + i]], 1);
}

// ---------------- single-block exclusive scan (N=40000) --------------------
__global__ void k_scan() {
    __shared__ int s[1024];
    int t = threadIdx.x;
    int carry = 0;
    for (int base = 0; base < NN; base += 1024) {
        int i = base + t;
        int v = (i < NN) ? g_deg[i] : 0;
        s[t] = v; __syncthreads();
        for (int off = 1; off < 1024; off <<= 1) {
            int add = (t >= off) ? s[t - off] : 0;
            __syncthreads();
            s[t] += add;
            __syncthreads();
        }
        int incl = s[t];
        if (i < NN) {
            g_rowptr[i] = carry + incl - v;
            g_cursor[i] = carry + incl - v;
        }
        int tot = s[1023];
        __syncthreads();
        carry += tot;
    }
    if (t == 0) g_rowptr[NN] = carry;   // == EP
}

// ---------------- fused scatter + edge exp ---------------------------------
// Counting-sort edges by dst and compute the 8 per-head exp(leaky_relu(..))
// values in the same pass, storing them at the sorted position. No max-shift:
// attention logits are ~N(0,2); exp stays well within fp32 range, and the
// final alpha = ex/denom is scale-invariant.
__global__ void k_scatter_edges(const int* __restrict__ ei) {
    int i = blockIdx.x * blockDim.x + threadIdx.x;
    if (i >= EP) return;
    int src, dst;
    if (i < EE) { src = ei[i]; dst = ei[EE + i]; }
    else        { dst = i - EE; src = dst; }

    const float4* as4 = (const float4*)(g_as + src * HH);
    const float4* ad4 = (const float4*)(g_ad + dst * HH);
    float4 r[2];
    #pragma unroll
    for (int p = 0; p < 2; p++) {
        float4 a = as4[p], b = ad4[p];
        float e0 = a.x + b.x, e1 = a.y + b.y, e2 = a.z + b.z, e3 = a.w + b.w;
        e0 = e0 > 0.f ? e0 : 0.2f * e0;
        e1 = e1 > 0.f ? e1 : 0.2f * e1;
        e2 = e2 > 0.f ? e2 : 0.2f * e2;
        e3 = e3 > 0.f ? e3 : 0.2f * e3;
        r[p] = make_float4(__expf(e0), __expf(e1), __expf(e2), __expf(e3));
    }
    int pos = atomicAdd(&g_cursor[dst], 1);
    g_srcs[pos] = src;
    float4* exo = (float4*)(g_exs + (size_t)pos * HH);
    exo[0] = r[0];
    exo[1] = r[1];
}

// ---------------- aggregation: warp per dst, denom in-register -------------
__global__ __launch_bounds__(256) void k_emb(int g, const int* __restrict__ route_vec) {
    int warp = threadIdx.x >> 5;
    int l    = threadIdx.x & 31;
    int dst  = blockIdx.x * 8 + warp;
    if (dst >= NN) return;

    int start = g_rowptr[dst];
    int end   = g_rowptr[dst + 1];

    float4 a0 = make_float4(0,0,0,0), a1 = a0, a2 = a0, a3 = a0;
    float dsum = 0.f;   // lanes 0..7 accumulate denom for head l

    for (int j = start; j < end; j++) {
        int src = g_srcs[j];
        float exv = (l < HH) ? g_exs[(size_t)j * HH + l] : 0.f;
        dsum += exv;
        float ea = __shfl_sync(0xffffffffu, exv, l >> 2);  // head (l>>2) numerator
        const float4* hp = (const float4*)(g_h + (size_t)src * HC + l * 16);
        float4 h0 = hp[0], h1 = hp[1], h2 = hp[2], h3 = hp[3];
        a0.x = fmaf(ea, h0.x, a0.x); a0.y = fmaf(ea, h0.y, a0.y);
        a0.z = fmaf(ea, h0.z, a0.z); a0.w = fmaf(ea, h0.w, a0.w);
        a1.x = fmaf(ea, h1.x, a1.x); a1.y = fmaf(ea, h1.y, a1.y);
        a1.z = fmaf(ea, h1.z, a1.z); a1.w = fmaf(ea, h1.w, a1.w);
        a2.x = fmaf(ea, h2.x, a2.x); a2.y = fmaf(ea, h2.y, a2.y);
        a2.z = fmaf(ea, h2.z, a2.z); a2.w = fmaf(ea, h2.w, a2.w);
        a3.x = fmaf(ea, h3.x, a3.x); a3.y = fmaf(ea, h3.y, a3.y);
        a3.z = fmaf(ea, h3.z, a3.z); a3.w = fmaf(ea, h3.w, a3.w);
    }

    // lane l<8 holds denom for head l; broadcast 1/denom to the 4 lanes of that head
    float dinv = 1.f / dsum;                       // valid on lanes 0..7
    float invh = __shfl_sync(0xffffffffu, dinv, l >> 2);

    a0.x *= invh; a0.y *= invh; a0.z *= invh; a0.w *= invh;
    a1.x *= invh; a1.y *= invh; a1.z *= invh; a1.w *= invh;
    a2.x *= invh; a2.y *= invh; a2.z *= invh; a2.w *= invh;
    a3.x *= invh; a3.y *= invh; a3.z *= invh; a3.w *= invh;

    int route = route_vec[dst];
    float* base = &g_agg[g][route * HC + l * 16];
    red4(base,      a0);
    red4(base + 4,  a1);
    red4(base + 8,  a2);
    red4(base + 12, a3);
}

// ---------------- U[which][r][k] = (agg + cnt*bias) . W_head_slice ---------
__global__ void k_U(const float* __restrict__ bias, const float* __restrict__ Whead) {
    __shared__ float sA[HC];
    int b = blockIdx.x;
    int which = b & 1;
    int r     = b >> 1;
    int t = threadIdx.x;
    float cnt = (float)g_cnt[which][r];
    for (int c = t; c < HC; c += blockDim.x)
        sA[c] = g_agg[which][r * HC + c] + cnt * bias[c];
    __syncthreads();
    if (t < KOUT) {
        float acc = 0.f;
        for (int c = 0; c < HC; c++)
            acc = fmaf(sA[c], Whead[(size_t)(which * HC + c) * WCOL + t], acc);
        g_U[which][r * 64 + t] = acc;
    }
}

// ---------------- logits ----------------------------------------------------
__global__ void k_logits(const float* __restrict__ bh) {
    int i = blockIdx.x * blockDim.x + threadIdx.x;
    if (i >= NLOG) return;
    int k  = i % KOUT;
    int r2 = (i / KOUT) % RR;
    int r1 = i / (KOUT * RR);
    g_logits[i] = g_U[0][r1 * 64 + k] + g_U[1][r2 * 64 + k] + bh[k];
}

// ---------------- global softmax over all 62400 logits ---------------------
__global__ void k_softmax(float* __restrict__ out) {
    __shared__ float s[1024];
    __shared__ float gm_sh, gs_sh;
    int t = threadIdx.x;

    float m = -1e30f;
    for (int i = t; i < NLOG; i += 1024) m = fmaxf(m, g_logits[i]);
    s[t] = m; __syncthreads();
    for (int off = 512; off > 0; off >>= 1) {
        if (t < off) s[t] = fmaxf(s[t], s[t + off]);
        __syncthreads();
    }
    if (t == 0) gm_sh = s[0];
    __syncthreads();
    float gm = gm_sh;
    __syncthreads();

    float sum = 0.f;
    for (int i = t; i < NLOG; i += 1024) sum += expf(g_logits[i] - gm);
    s[t] = sum; __syncthreads();
    for (int off = 512; off > 0; off >>= 1) {
        if (t < off) s[t] += s[t + off];
        __syncthreads();
    }
    if (t == 0) gs_sh = s[0];
    __syncthreads();
    float inv = 1.f / gs_sh;

    for (int i = t; i < NLOG; i += 1024)
        out[i] = expf(g_logits[i] - gm) * inv;
}

// ---------------- launch ----------------------------------------------------
extern "C" void kernel_launch(void* const* d_in, const int* in_sizes, int n_in,
                              void* d_out, int out_size) {
    const float* x1   = (const float*)d_in[0];
    const int*   ei1  = (const int*)  d_in[1];
    const int*   rv1  = (const int*)  d_in[3];
    const float* x2   = (const float*)d_in[5];
    const int*   ei2  = (const int*)  d_in[6];
    const int*   rv2  = (const int*)  d_in[8];
    const float* Wg   = (const float*)d_in[10];
    const float* atS  = (const float*)d_in[11];
    const float* atD  = (const float*)d_in[12];
    const float* bg   = (const float*)d_in[13];
    const float* Wh   = (const float*)d_in[14];
    const float* bh   = (const float*)d_in[15];
    float* out = (float*)d_out;

    const int TB = 256;
    const int GN  = (NN + TB - 1) / TB;      // 157
    const int GE  = (EE + TB - 1) / TB;      // 1563
    const int GEP = (EP + TB - 1) / TB;      // 1719
    const int GEMM_BLOCKS = 592;             // 4 waves of warps over 40000 nodes
    const int GEMB = (NN + 7) / 8;           // 5000

    const float* xs[2]  = { x1, x2 };
    const int*   eis[2] = { ei1, ei2 };
    const int*   rvs[2] = { rv1, rv2 };

    for (int g = 0; g < 2; g++) {
        k_zero<<<1, 64>>>(g);
        k_init<<<GN, TB>>>(g, rvs[g]);
        k_gemm<<<GEMM_BLOCKS, TB>>>(xs[g], Wg, atS, atD);
        k_deg<<<GE, TB>>>(eis[g]);
        k_scan<<<1, 1024>>>();
        k_scatter_edges<<<GEP, TB>>>(eis[g]);
        k_emb<<<GEMB, TB>>>(g, rvs[g]);
    }
    k_U<<<2 * RR, 128>>>(bg, Wh);
    k_logits<<<(NLOG + TB - 1) / TB, TB>>>(bh);
    k_softmax<<<1, 1024>>>(out);
    (void)in_sizes; (void)n_in; (void)out_size;
}

// round 3
// speedup vs baseline: 1.1509x; 1.1509x over previous
#include <cuda_runtime.h>
#include <cstdint>

// Problem constants (fixed by the dataset's setup_inputs)
#define NN   40000
#define EE   400000
#define EP   (EE + NN)     // edges + self loops
#define HH   8
#define CC   64
#define HC   512           // H*C
#define FF   16
#define RR   40            // n_routes1 == n_routes2 == 40
#define KOUT 39            // max_to_swap - 1
#define WCOL 61            // MAXR + 1 columns of W_head
#define NLOG (RR * RR * KOUT)
#define NCH  40            // scan chunks of 1024 covering 40960 >= NN

// ---------------- scratch (reused across the two graphs, stream-ordered) ---
__device__ float g_h[(size_t)NN * HC];        // 82 MB — L2 resident
__device__ float g_as[NN * HH];
__device__ float g_ad[NN * HH];
__device__ float g_exs[(size_t)EP * HH];      // dst-sorted exp values, 14 MB
__device__ int   g_deg[NN];
__device__ int   g_rowptr[NN + 1];
__device__ int   g_cursor[NN];
__device__ int   g_srcs[EP];                  // dst-sorted src ids
__device__ int   g_bsum[NCH];
__device__ int   g_boff[NCH];
__device__ float g_agg[2][RR * HC];
__device__ int   g_cnt[2][RR];
__device__ float g_U[2][RR * 64];
__device__ float g_logits[NLOG];

__device__ __forceinline__ void red4(float* p, float4 v) {
    asm volatile("red.global.add.v4.f32 [%0], {%1, %2, %3, %4};"
                 :: "l"(p), "f"(v.x), "f"(v.y), "f"(v.z), "f"(v.w) : "memory");
}

// ---------------- one-time zero of both graphs' route accumulators ---------
__global__ void k_zero_all() {
    int i = blockIdx.x * blockDim.x + threadIdx.x;
    if (i < 2 * RR * HC) ((float*)g_agg)[i] = 0.f;
    if (i < 2 * RR)      ((int*)g_cnt)[i] = 0;
}

// ---------------- per-graph init (+ route node counts) ---------------------
__global__ void k_init(int g, const int* __restrict__ route_vec) {
    int i = blockIdx.x * blockDim.x + threadIdx.x;
    if (i < NN) {
        g_deg[i] = 1;  // self loop
        atomicAdd(&g_cnt[g][route_vec[i]], 1);
    }
}

// ---------------- fused GEMM h = x@W + attention dots ----------------------
__global__ __launch_bounds__(256) void k_gemm(
    const float* __restrict__ x, const float* __restrict__ W,
    const float* __restrict__ attS, const float* __restrict__ attD)
{
    __shared__ float Wsh[FF * HC];  // 32 KB
    int t = threadIdx.x;
    for (int i = t; i < FF * HC; i += blockDim.x) Wsh[i] = W[i];
    __syncthreads();

    int l    = t & 31;
    int wid  = blockIdx.x * (blockDim.x >> 5) + (t >> 5);
    int nwrp = gridDim.x * (blockDim.x >> 5);

    for (int n = wid; n < NN; n += nwrp) {
        float v = (l < FF) ? x[n * FF + l] : 0.f;
        float xr[FF];
        #pragma unroll
        for (int f = 0; f < FF; f++) xr[f] = __shfl_sync(0xffffffffu, v, f);

        float hacc[16];
        #pragma unroll
        for (int k = 0; k < 16; k++) {
            float a = 0.f;
            #pragma unroll
            for (int f = 0; f < FF; f++)
                a = fmaf(xr[f], Wsh[f * HC + 32 * k + l], a);
            hacc[k] = a;
            g_h[(size_t)n * HC + 32 * k + l] = a;   // coalesced 128B per k
        }
        #pragma unroll
        for (int h = 0; h < HH; h++) {
            float ps = fmaf(hacc[2*h],   attS[h*64 + l],
                      hacc[2*h+1] * attS[h*64 + 32 + l]);
            float pd = fmaf(hacc[2*h],   attD[h*64 + l],
                      hacc[2*h+1] * attD[h*64 + 32 + l]);
            #pragma unroll
            for (int o = 16; o > 0; o >>= 1) {
                ps += __shfl_xor_sync(0xffffffffu, ps, o);
                pd += __shfl_xor_sync(0xffffffffu, pd, o);
            }
            if (l == 0) { g_as[n*HH + h] = ps; g_ad[n*HH + h] = pd; }
        }
    }
}

// ---------------- degree histogram -----------------------------------------
__global__ void k_deg(const int* __restrict__ ei) {
    int i = blockIdx.x * blockDim.x + threadIdx.x;
    if (i < EE) atomicAdd(&g_deg[ei[EE + i]], 1);
}

// ---------------- parallel 3-stage scan -------------------------------------
__global__ void k_blocksum() {
    __shared__ int s[1024];
    int b = blockIdx.x, t = threadIdx.x;
    int i = b * 1024 + t;
    s[t] = (i < NN) ? g_deg[i] : 0;
    __syncthreads();
    for (int off = 512; off > 0; off >>= 1) {
        if (t < off) s[t] += s[t + off];
        __syncthreads();
    }
    if (t == 0) g_bsum[b] = s[0];
}

__global__ void k_bscan() {
    int c = 0;
    #pragma unroll
    for (int b = 0; b < NCH; b++) { g_boff[b] = c; c += g_bsum[b]; }
    g_rowptr[NN] = c;   // == EP
}

__global__ void k_offsets() {
    __shared__ int s[1024];
    int b = blockIdx.x, t = threadIdx.x;
    int i = b * 1024 + t;
    int v = (i < NN) ? g_deg[i] : 0;
    s[t] = v;
    __syncthreads();
    for (int off = 1; off < 1024; off <<= 1) {
        int a = (t >= off) ? s[t - off] : 0;
        __syncthreads();
        s[t] += a;
        __syncthreads();
    }
    if (i < NN) {
        int ex = g_boff[b] + s[t] - v;   // exclusive
        g_rowptr[i] = ex;
        g_cursor[i] = ex;
    }
}

// ---------------- fused scatter + edge exp ---------------------------------
// Counting-sort edges by dst and compute the 8 per-head exp(leaky_relu(..))
// values in the same pass, storing them at the sorted position. No max-shift:
// attention logits are ~N(0,2); exp stays well within fp32 range, and the
// final alpha = ex/denom is scale-invariant.
__global__ void k_scatter_edges(const int* __restrict__ ei) {
    int i = blockIdx.x * blockDim.x + threadIdx.x;
    if (i >= EP) return;
    int src, dst;
    if (i < EE) { src = ei[i]; dst = ei[EE + i]; }
    else        { dst = i - EE; src = dst; }

    const float4* as4 = (const float4*)(g_as + src * HH);
    const float4* ad4 = (const float4*)(g_ad + dst * HH);
    float4 r[2];
    #pragma unroll
    for (int p = 0; p < 2; p++) {
        float4 a = as4[p], b = ad4[p];
        float e0 = a.x + b.x, e1 = a.y + b.y, e2 = a.z + b.z, e3 = a.w + b.w;
        e0 = e0 > 0.f ? e0 : 0.2f * e0;
        e1 = e1 > 0.f ? e1 : 0.2f * e1;
        e2 = e2 > 0.f ? e2 : 0.2f * e2;
        e3 = e3 > 0.f ? e3 : 0.2f * e3;
        r[p] = make_float4(__expf(e0), __expf(e1), __expf(e2), __expf(e3));
    }
    int pos = atomicAdd(&g_cursor[dst], 1);
    g_srcs[pos] = src;
    float4* exo = (float4*)(g_exs + (size_t)pos * HH);
    exo[0] = r[0];
    exo[1] = r[1];
}

// ---------------- aggregation: warp per dst, denom in-register -------------
__global__ __launch_bounds__(256) void k_emb(int g, const int* __restrict__ route_vec) {
    int warp = threadIdx.x >> 5;
    int l    = threadIdx.x & 31;
    int dst  = blockIdx.x * 8 + warp;
    if (dst >= NN) return;

    int start = g_rowptr[dst];
    int end   = g_rowptr[dst + 1];

    float4 a0 = make_float4(0,0,0,0), a1 = a0, a2 = a0, a3 = a0;
    float dsum = 0.f;   // lanes 0..7 accumulate denom for head l

    int j = start;
    // unrolled-by-2: 8 independent float4 loads in flight
    for (; j + 1 < end; j += 2) {
        int s0 = g_srcs[j], s1 = g_srcs[j + 1];
        float e0 = (l < HH) ? g_exs[(size_t)j * HH + l] : 0.f;
        float e1 = (l < HH) ? g_exs[(size_t)(j + 1) * HH + l] : 0.f;
        dsum += e0 + e1;
        float ea0 = __shfl_sync(0xffffffffu, e0, l >> 2);
        float ea1 = __shfl_sync(0xffffffffu, e1, l >> 2);
        const float4* hp0 = (const float4*)(g_h + (size_t)s0 * HC + l * 16);
        const float4* hp1 = (const float4*)(g_h + (size_t)s1 * HC + l * 16);
        float4 p0 = hp0[0], p1 = hp0[1], p2 = hp0[2], p3 = hp0[3];
        float4 q0 = hp1[0], q1 = hp1[1], q2 = hp1[2], q3 = hp1[3];
        a0.x = fmaf(ea0, p0.x, a0.x); a0.y = fmaf(ea0, p0.y, a0.y);
        a0.z = fmaf(ea0, p0.z, a0.z); a0.w = fmaf(ea0, p0.w, a0.w);
        a1.x = fmaf(ea0, p1.x, a1.x); a1.y = fmaf(ea0, p1.y, a1.y);
        a1.z = fmaf(ea0, p1.z, a1.z); a1.w = fmaf(ea0, p1.w, a1.w);
        a2.x = fmaf(ea0, p2.x, a2.x); a2.y = fmaf(ea0, p2.y, a2.y);
        a2.z = fmaf(ea0, p2.z, a2.z); a2.w = fmaf(ea0, p2.w, a2.w);
        a3.x = fmaf(ea0, p3.x, a3.x); a3.y = fmaf(ea0, p3.y, a3.y);
        a3.z = fmaf(ea0, p3.z, a3.z); a3.w = fmaf(ea0, p3.w, a3.w);
        a0.x = fmaf(ea1, q0.x, a0.x); a0.y = fmaf(ea1, q0.y, a0.y);
        a0.z = fmaf(ea1, q0.z, a0.z); a0.w = fmaf(ea1, q0.w, a0.w);
        a1.x = fmaf(ea1, q1.x, a1.x); a1.y = fmaf(ea1, q1.y, a1.y);
        a1.z = fmaf(ea1, q1.z, a1.z); a1.w = fmaf(ea1, q1.w, a1.w);
        a2.x = fmaf(ea1, q2.x, a2.x); a2.y = fmaf(ea1, q2.y, a2.y);
        a2.z = fmaf(ea1, q2.z, a2.z); a2.w = fmaf(ea1, q2.w, a2.w);
        a3.x = fmaf(ea1, q3.x, a3.x); a3.y = fmaf(ea1, q3.y, a3.y);
        a3.z = fmaf(ea1, q3.z, a3.z); a3.w = fmaf(ea1, q3.w, a3.w);
    }
    if (j < end) {
        int src = g_srcs[j];
        float exv = (l < HH) ? g_exs[(size_t)j * HH + l] : 0.f;
        dsum += exv;
        float ea = __shfl_sync(0xffffffffu, exv, l >> 2);
        const float4* hp = (const float4*)(g_h + (size_t)src * HC + l * 16);
        float4 h0 = hp[0], h1 = hp[1], h2 = hp[2], h3 = hp[3];
        a0.x = fmaf(ea, h0.x, a0.x); a0.y = fmaf(ea, h0.y, a0.y);
        a0.z = fmaf(ea, h0.z, a0.z); a0.w = fmaf(ea, h0.w, a0.w);
        a1.x = fmaf(ea, h1.x, a1.x); a1.y = fmaf(ea, h1.y, a1.y);
        a1.z = fmaf(ea, h1.z, a1.z); a1.w = fmaf(ea, h1.w, a1.w);
        a2.x = fmaf(ea, h2.x, a2.x); a2.y = fmaf(ea, h2.y, a2.y);
        a2.z = fmaf(ea, h2.z, a2.z); a2.w = fmaf(ea, h2.w, a2.w);
        a3.x = fmaf(ea, h3.x, a3.x); a3.y = fmaf(ea, h3.y, a3.y);
        a3.z = fmaf(ea, h3.z, a3.z); a3.w = fmaf(ea, h3.w, a3.w);
    }

    // lane l<8 holds denom for head l; broadcast 1/denom to the 4 lanes of that head
    float dinv = 1.f / dsum;                       // valid on lanes 0..7
    float invh = __shfl_sync(0xffffffffu, dinv, l >> 2);

    a0.x *= invh; a0.y *= invh; a0.z *= invh; a0.w *= invh;
    a1.x *= invh; a1.y *= invh; a1.z *= invh; a1.w *= invh;
    a2.x *= invh; a2.y *= invh; a2.z *= invh; a2.w *= invh;
    a3.x *= invh; a3.y *= invh; a3.z *= invh; a3.w *= invh;

    int route = route_vec[dst];
    float* base = &g_agg[g][route * HC + l * 16];
    red4(base,      a0);
    red4(base + 4,  a1);
    red4(base + 8,  a2);
    red4(base + 12, a3);
}

// ---------------- U[which][r][k] = (agg + cnt*bias) . W_head_slice ---------
__global__ void k_U(const float* __restrict__ bias, const float* __restrict__ Whead) {
    __shared__ float sA[HC];
    int b = blockIdx.x;
    int which = b & 1;
    int r     = b >> 1;
    int t = threadIdx.x;
    float cnt = (float)g_cnt[which][r];
    for (int c = t; c < HC; c += blockDim.x)
        sA[c] = g_agg[which][r * HC + c] + cnt * bias[c];
    __syncthreads();
    if (t < KOUT) {
        float acc = 0.f;
        for (int c = 0; c < HC; c++)
            acc = fmaf(sA[c], Whead[(size_t)(which * HC + c) * WCOL + t], acc);
        g_U[which][r * 64 + t] = acc;
    }
}

// ---------------- logits ----------------------------------------------------
__global__ void k_logits(const float* __restrict__ bh) {
    int i = blockIdx.x * blockDim.x + threadIdx.x;
    if (i >= NLOG) return;
    int k  = i % KOUT;
    int r2 = (i / KOUT) % RR;
    int r1 = i / (KOUT * RR);
    g_logits[i] = g_U[0][r1 * 64 + k] + g_U[1][r2 * 64 + k] + bh[k];
}

// ---------------- global softmax over all 62400 logits ---------------------
__global__ void k_softmax(float* __restrict__ out) {
    __shared__ float s[1024];
    __shared__ float gm_sh, gs_sh;
    int t = threadIdx.x;

    float m = -1e30f;
    for (int i = t; i < NLOG; i += 1024) m = fmaxf(m, g_logits[i]);
    s[t] = m; __syncthreads();
    for (int off = 512; off > 0; off >>= 1) {
        if (t < off) s[t] = fmaxf(s[t], s[t + off]);
        __syncthreads();
    }
    if (t == 0) gm_sh = s[0];
    __syncthreads();
    float gm = gm_sh;
    __syncthreads();

    float sum = 0.f;
    for (int i = t; i < NLOG; i += 1024) sum += expf(g_logits[i] - gm);
    s[t] = sum; __syncthreads();
    for (int off = 512; off > 0; off >>= 1) {
        if (t < off) s[t] += s[t + off];
        __syncthreads();
    }
    if (t == 0) gs_sh = s[0];
    __syncthreads();
    float inv = 1.f / gs_sh;

    for (int i = t; i < NLOG; i += 1024)
        out[i] = expf(g_logits[i] - gm) * inv;
}

// ---------------- launch ----------------------------------------------------
extern "C" void kernel_launch(void* const* d_in, const int* in_sizes, int n_in,
                              void* d_out, int out_size) {
    const float* x1   = (const float*)d_in[0];
    const int*   ei1  = (const int*)  d_in[1];
    const int*   rv1  = (const int*)  d_in[3];
    const float* x2   = (const float*)d_in[5];
    const int*   ei2  = (const int*)  d_in[6];
    const int*   rv2  = (const int*)  d_in[8];
    const float* Wg   = (const float*)d_in[10];
    const float* atS  = (const float*)d_in[11];
    const float* atD  = (const float*)d_in[12];
    const float* bg   = (const float*)d_in[13];
    const float* Wh   = (const float*)d_in[14];
    const float* bh   = (const float*)d_in[15];
    float* out = (float*)d_out;

    const int TB = 256;
    const int GN  = (NN + TB - 1) / TB;      // 157
    const int GE  = (EE + TB - 1) / TB;      // 1563
    const int GEP = (EP + TB - 1) / TB;      // 1719
    const int GEMM_BLOCKS = 592;
    const int GEMB = (NN + 7) / 8;           // 5000

    const float* xs[2]  = { x1, x2 };
    const int*   eis[2] = { ei1, ei2 };
    const int*   rvs[2] = { rv1, rv2 };

    k_zero_all<<<(2 * RR * HC + TB - 1) / TB, TB>>>();

    for (int g = 0; g < 2; g++) {
        k_init<<<GN, TB>>>(g, rvs[g]);
        k_gemm<<<GEMM_BLOCKS, TB>>>(xs[g], Wg, atS, atD);
        k_deg<<<GE, TB>>>(eis[g]);
        k_blocksum<<<NCH, 1024>>>();
        k_bscan<<<1, 1>>>();
        k_offsets<<<NCH, 1024>>>();
        k_scatter_edges<<<GEP, TB>>>(eis[g]);
        k_emb<<<GEMB, TB>>>(g, rvs[g]);
    }
    k_U<<<2 * RR, 128>>>(bg, Wh);
    k_logits<<<(NLOG + TB - 1) / TB, TB>>>(bh);
    k_softmax<<<1, 1024>>>(out);
    (void)in_sizes; (void)n_in; (void)out_size;
}